// round 1
// baseline (speedup 1.0000x reference)
#include <cuda_runtime.h>
#include <math.h>

#define Bn   8
#define Cn   64
#define Hn   128
#define Wn   128
#define OUTn 128
#define Kn   9

// Scratch (device globals: allocation-free rule)
__device__ float g_xt [Bn*Hn*Wn*Cn];     // x transposed to NHWC (33.5 MB)
__device__ float g_wt [Cn*Kn*OUTn];      // w_conv transposed to [ck][o]
__device__ float g_off[Bn*Hn*Wn*27];     // per-pixel {dy,dx,mask} x 9 taps (14 MB)

// ---------------------------------------------------------------------------
// Kernel 1: transpose x NCHW -> NHWC (channel-contiguous for vector gathers)
// ---------------------------------------------------------------------------
__global__ void xpose_kernel(const float* __restrict__ x) {
    __shared__ float t[64][33];
    int b = blockIdx.z, y = blockIdx.y, x0 = blockIdx.x * 32;
    int tx = threadIdx.x & 31, ty = threadIdx.x >> 5;
    #pragma unroll
    for (int i = 0; i < 8; i++) {
        int c = i * 8 + ty;
        t[c][tx] = x[((b * Cn + c) * Hn + y) * Wn + x0 + tx];
    }
    __syncthreads();
    int c2 = threadIdx.x & 63, col2 = threadIdx.x >> 6;
    #pragma unroll
    for (int j = 0; j < 8; j++) {
        int col = col2 + j * 4;
        g_xt[((b * Hn + y) * Wn + x0 + col) * Cn + c2] = t[c2][col];
    }
}

// ---------------------------------------------------------------------------
// Kernel 2: transpose w_conv (OUT,C,3,3) -> Wt[ck][o], ck = c*9 + k
// ---------------------------------------------------------------------------
__global__ void wpose_kernel(const float* __restrict__ w_conv) {
    int i = blockIdx.x * 256 + threadIdx.x;
    if (i < Cn * Kn * OUTn) {
        int ck = i >> 7, o = i & 127;
        g_wt[i] = w_conv[o * (Cn * Kn) + ck];
    }
}

// ---------------------------------------------------------------------------
// Kernel 3: fused offset(18ch) + mask(9ch) 3x3 conv, sigmoid on mask.
// One block per (b,h) row; 128 threads (one per w). All 27x64x9 weights in smem.
// Output layout: g_off[((b*H+h)*W+w)*27 + k*3 + {0:dy,1:dx,2:mask}]
// ---------------------------------------------------------------------------
__global__ void offmask_kernel(const float* __restrict__ x,
                               const float* __restrict__ w_off,
                               const float* __restrict__ b_off,
                               const float* __restrict__ w_mask,
                               const float* __restrict__ b_mask) {
    extern __shared__ float sm[];
    float* wsh = sm;                  // 27*576
    float* bsh = sm + 27 * 576;       // 27
    float* xs  = sm + 27 * 576 + 32;  // 3*130

    int h = blockIdx.x, b = blockIdx.y;
    int tid = threadIdx.x;  // 0..127 == w

    for (int i = tid; i < 27 * 576; i += 128) {
        int ch = i / 576, r = i - ch * 576;
        wsh[i] = (ch < 18) ? w_off[i] : w_mask[(ch - 18) * 576 + r];
    }
    if (tid < 27) bsh[tid] = (tid < 18) ? b_off[tid] : b_mask[tid - 18];

    float acc[27];
    #pragma unroll
    for (int i = 0; i < 27; i++) acc[i] = 0.f;

    for (int c = 0; c < Cn; c++) {
        __syncthreads();  // guards wsh on c=0, xs reuse afterwards
        #pragma unroll
        for (int r = 0; r < 3; r++) {
            int y = h + r - 1;
            float v = 0.f;
            if (y >= 0 && y < Hn) v = x[((b * Cn + c) * Hn + y) * Wn + tid];
            xs[r * 130 + tid + 1] = v;
        }
        if (tid < 6) xs[(tid >> 1) * 130 + ((tid & 1) ? 129 : 0)] = 0.f;
        __syncthreads();
        #pragma unroll
        for (int r = 0; r < 3; r++) {
            float x0 = xs[r * 130 + tid];
            float x1 = xs[r * 130 + tid + 1];
            float x2 = xs[r * 130 + tid + 2];
            const float* wp = wsh + c * 9 + r * 3;
            #pragma unroll
            for (int ch = 0; ch < 27; ch++) {
                const float* w = wp + ch * 576;
                acc[ch] += w[0] * x0 + w[1] * x1 + w[2] * x2;
            }
        }
    }

    float* op = g_off + ((b * Hn + h) * Wn + tid) * 27;
    #pragma unroll
    for (int k = 0; k < Kn; k++) {
        op[k * 3 + 0] = acc[2 * k]     + bsh[2 * k];
        op[k * 3 + 1] = acc[2 * k + 1] + bsh[2 * k + 1];
        float t = acc[18 + k] + bsh[18 + k];
        op[k * 3 + 2] = 1.f / (1.f + expf(-t));
    }
}

// ---------------------------------------------------------------------------
// Kernel 4: fused bilinear sample + GEMM.
// Tile: 128 pixels (one (b,h) row) x 128 outputs. Chunks of 8 channels (72 ck).
// Threads 256 as (tp 0..15: 8 px each, to 0..15: 8 out each). 8x8 reg blocking.
// ---------------------------------------------------------------------------
__global__ void __launch_bounds__(256, 2)
main_kernel(float* __restrict__ out) {
    extern __shared__ float sm[];
    float* Ssh = sm;             // [72][128] sampled (ck-major)
    float* Wsh = sm + 72 * 128;  // [72][128] weights (ck-major)

    int h = blockIdx.x, b = blockIdx.y;
    int tid = threadIdx.x;
    int tp = tid & 15;   // pixel group: p in [tp*8, tp*8+8)
    int to = tid >> 4;   // out group:   o in [to*8, to*8+8)

    float acc[8][8];
    #pragma unroll
    for (int i = 0; i < 8; i++)
        #pragma unroll
        for (int j = 0; j < 8; j++) acc[i][j] = 0.f;

    int hwb = (b * Hn + h) * Wn;

    for (int c0 = 0; c0 < Cn; c0 += 8) {
        __syncthreads();  // prior GEMM finished reading smem

        // Load weight chunk (72 x 128, contiguous)
        {
            const float* wsrc = g_wt + c0 * 9 * OUTn;
            #pragma unroll
            for (int i = 0; i < 9216; i += 256) Wsh[i + tid] = wsrc[i + tid];
        }

        // Sample 128 px x 9 taps x 8 channels into Ssh
        for (int idx = tid; idx < Wn * Kn; idx += 256) {
            int p = idx & (Wn - 1);
            int k = idx >> 7;
            const float* op = g_off + (hwb + p) * 27 + k * 3;
            float dy = op[0], dx = op[1], m = op[2];
            int ky = k / 3, kx = k - ky * 3;
            float gy = (float)(h - 1 + ky) + dy;
            float gx = (float)(p - 1 + kx) + dx;
            float y0f = floorf(gy), x0f = floorf(gx);
            float wy = gy - y0f, wx = gx - x0f;
            int y0 = (int)y0f, x0i = (int)x0f;

            float s[8];
            #pragma unroll
            for (int cl = 0; cl < 8; cl++) s[cl] = 0.f;

            #pragma unroll
            for (int cor = 0; cor < 4; cor++) {
                int yi = y0 + (cor >> 1);
                int xi = x0i + (cor & 1);
                float wgt = ((cor >> 1) ? wy : 1.f - wy) *
                            ((cor & 1)  ? wx : 1.f - wx) * m;
                if (yi < 0 || yi >= Hn || xi < 0 || xi >= Wn) wgt = 0.f;
                int yc = min(max(yi, 0), Hn - 1);
                int xc = min(max(xi, 0), Wn - 1);
                const float4* xp =
                    (const float4*)(g_xt + ((b * Hn + yc) * Wn + xc) * Cn + c0);
                float4 va = xp[0], vb = xp[1];
                s[0] += wgt * va.x; s[1] += wgt * va.y;
                s[2] += wgt * va.z; s[3] += wgt * va.w;
                s[4] += wgt * vb.x; s[5] += wgt * vb.y;
                s[6] += wgt * vb.z; s[7] += wgt * vb.w;
            }
            #pragma unroll
            for (int cl = 0; cl < 8; cl++)
                Ssh[(cl * 9 + k) * 128 + p] = s[cl];
        }
        __syncthreads();

        // GEMM on the 72-ck chunk
        #pragma unroll 4
        for (int ckl = 0; ckl < 72; ckl++) {
            const float4* sv = (const float4*)(Ssh + ckl * 128 + tp * 8);
            float4 sa = sv[0], sb = sv[1];
            const float4* wv = (const float4*)(Wsh + ckl * 128 + to * 8);
            float4 wa = wv[0], wb = wv[1];
            float sr[8] = {sa.x, sa.y, sa.z, sa.w, sb.x, sb.y, sb.z, sb.w};
            float wr[8] = {wa.x, wa.y, wa.z, wa.w, wb.x, wb.y, wb.z, wb.w};
            #pragma unroll
            for (int oi = 0; oi < 8; oi++)
                #pragma unroll
                for (int pi = 0; pi < 8; pi++)
                    acc[oi][pi] += wr[oi] * sr[pi];
        }
    }

    // Coalesced epilogue: out is NCHW; each thread owns 8 contiguous w's.
    #pragma unroll
    for (int oi = 0; oi < 8; oi++) {
        float* orow = out +
            ((size_t)(b * OUTn + to * 8 + oi) * Hn + h) * Wn + tp * 8;
        ((float4*)orow)[0] = make_float4(acc[oi][0], acc[oi][1], acc[oi][2], acc[oi][3]);
        ((float4*)orow)[1] = make_float4(acc[oi][4], acc[oi][5], acc[oi][6], acc[oi][7]);
    }
}

// ---------------------------------------------------------------------------
extern "C" void kernel_launch(void* const* d_in, const int* in_sizes, int n_in,
                              void* d_out, int out_size) {
    const float* x      = (const float*)d_in[0];
    const float* w_off  = (const float*)d_in[1];
    const float* b_off  = (const float*)d_in[2];
    const float* w_mask = (const float*)d_in[3];
    const float* b_mask = (const float*)d_in[4];
    const float* w_conv = (const float*)d_in[5];
    float* out = (float*)d_out;

    // >48KB dynamic smem opt-in (idempotent; no allocation, graph-safe)
    cudaFuncSetAttribute(offmask_kernel,
                         cudaFuncAttributeMaxDynamicSharedMemorySize, 65536);
    cudaFuncSetAttribute(main_kernel,
                         cudaFuncAttributeMaxDynamicSharedMemorySize, 75776);

    xpose_kernel<<<dim3(4, 128, 8), 256>>>(x);
    wpose_kernel<<<dim3((Cn * Kn * OUTn + 255) / 256), 256>>>(w_conv);

    size_t smA = (size_t)(27 * 576 + 32 + 3 * 130 + 32) * sizeof(float);
    offmask_kernel<<<dim3(Hn, Bn), 128, smA>>>(x, w_off, b_off, w_mask, b_mask);

    main_kernel<<<dim3(Hn, Bn), 256, 72 * 128 * 2 * sizeof(float)>>>(out);
}

// round 3
// speedup vs baseline: 1.2490x; 1.2490x over previous
#include <cuda_runtime.h>
#include <cuda_bf16.h>
#include <math.h>
#include <stdint.h>

#define Bn   8
#define Cn   64
#define Hn   128
#define Wn   128
#define OUTn 128
#define Kn   9

// Scratch (device globals: allocation-free rule)
__device__ float    g_xt  [Bn*Hn*Wn*Cn];   // x transposed to NHWC
__device__ float    g_off [Bn*Hn*Wn*27];   // per-pixel {dy,dx,mask} x 9 taps
__device__ uint32_t g_wbhi[Kn*OUTn*32];    // w_conv bf16-hi, [tap][o][kw] packed pairs
__device__ uint32_t g_wblo[Kn*OUTn*32];    // w_conv bf16-lo

// ---------------------------------------------------------------------------
__device__ __forceinline__ uint32_t pack_bf16(float a, float b) {
    return (uint32_t)__bfloat16_as_ushort(__float2bfloat16_rn(a)) |
           ((uint32_t)__bfloat16_as_ushort(__float2bfloat16_rn(b)) << 16);
}
__device__ __forceinline__ void split2(float v, float& hi, float& lo) {
    __nv_bfloat16 h = __float2bfloat16_rn(v);
    hi = __bfloat162float(h);
    lo = v - hi;
}
__device__ __forceinline__ void mma16816(float* c, const uint32_t* a, const uint32_t* b) {
    asm volatile(
        "mma.sync.aligned.m16n8k16.row.col.f32.bf16.bf16.f32 "
        "{%0,%1,%2,%3}, {%4,%5,%6,%7}, {%8,%9}, {%0,%1,%2,%3};"
        : "+f"(c[0]), "+f"(c[1]), "+f"(c[2]), "+f"(c[3])
        : "r"(a[0]), "r"(a[1]), "r"(a[2]), "r"(a[3]), "r"(b[0]), "r"(b[1]));
}

// ---------------------------------------------------------------------------
// Kernel 1: transpose x NCHW -> NHWC
// ---------------------------------------------------------------------------
__global__ void xpose_kernel(const float* __restrict__ x) {
    __shared__ float t[64][33];
    int b = blockIdx.z, y = blockIdx.y, x0 = blockIdx.x * 32;
    int tx = threadIdx.x & 31, ty = threadIdx.x >> 5;
    #pragma unroll
    for (int i = 0; i < 8; i++) {
        int c = i * 8 + ty;
        t[c][tx] = x[((b * Cn + c) * Hn + y) * Wn + x0 + tx];
    }
    __syncthreads();
    int c2 = threadIdx.x & 63, col2 = threadIdx.x >> 6;
    #pragma unroll
    for (int j = 0; j < 8; j++) {
        int col = col2 + j * 4;
        g_xt[((b * Hn + y) * Wn + x0 + col) * Cn + c2] = t[c2][col];
    }
}

// ---------------------------------------------------------------------------
// Kernel 2: split w_conv (OUT,C,3,3) into bf16 hi/lo, layout [tap][o][kw]
// ---------------------------------------------------------------------------
__global__ void wpose_kernel(const float* __restrict__ w_conv) {
    int i = blockIdx.x * 256 + threadIdx.x;
    if (i < Kn * OUTn * 32) {
        int tap = i >> 12, rem = i & 4095;
        int o = rem >> 5, kw = rem & 31;
        int c0 = kw * 2;
        float f0 = w_conv[o * 576 + c0 * 9 + tap];
        float f1 = w_conv[o * 576 + (c0 + 1) * 9 + tap];
        float h0, l0, h1, l1;
        split2(f0, h0, l0);
        split2(f1, h1, l1);
        g_wbhi[i] = pack_bf16(h0, h1);
        g_wblo[i] = pack_bf16(l0, l1);
    }
}

// ---------------------------------------------------------------------------
// Kernel 3: fused offset(18ch) + mask(9ch) 3x3 conv, sigmoid on mask.
// ---------------------------------------------------------------------------
__global__ void offmask_kernel(const float* __restrict__ x,
                               const float* __restrict__ w_off,
                               const float* __restrict__ b_off,
                               const float* __restrict__ w_mask,
                               const float* __restrict__ b_mask) {
    extern __shared__ float sm[];
    float* wsh = sm;
    float* bsh = sm + 27 * 576;
    float* xs  = sm + 27 * 576 + 32;

    int h = blockIdx.x, b = blockIdx.y;
    int tid = threadIdx.x;

    for (int i = tid; i < 27 * 576; i += 128) {
        int ch = i / 576, r = i - ch * 576;
        wsh[i] = (ch < 18) ? w_off[i] : w_mask[(ch - 18) * 576 + r];
    }
    if (tid < 27) bsh[tid] = (tid < 18) ? b_off[tid] : b_mask[tid - 18];

    float acc[27];
    #pragma unroll
    for (int i = 0; i < 27; i++) acc[i] = 0.f;

    for (int c = 0; c < Cn; c++) {
        __syncthreads();
        #pragma unroll
        for (int r = 0; r < 3; r++) {
            int y = h + r - 1;
            float v = 0.f;
            if (y >= 0 && y < Hn) v = x[((b * Cn + c) * Hn + y) * Wn + tid];
            xs[r * 130 + tid + 1] = v;
        }
        if (tid < 6) xs[(tid >> 1) * 130 + ((tid & 1) ? 129 : 0)] = 0.f;
        __syncthreads();
        #pragma unroll
        for (int r = 0; r < 3; r++) {
            float x0 = xs[r * 130 + tid];
            float x1 = xs[r * 130 + tid + 1];
            float x2 = xs[r * 130 + tid + 2];
            const float* wp = wsh + c * 9 + r * 3;
            #pragma unroll
            for (int ch = 0; ch < 27; ch++) {
                const float* w = wp + ch * 576;
                acc[ch] += w[0] * x0 + w[1] * x1 + w[2] * x2;
            }
        }
    }

    float* op = g_off + ((b * Hn + h) * Wn + tid) * 27;
    #pragma unroll
    for (int k = 0; k < Kn; k++) {
        op[k * 3 + 0] = acc[2 * k]     + bsh[2 * k];
        op[k * 3 + 1] = acc[2 * k + 1] + bsh[2 * k + 1];
        float t = acc[18 + k] + bsh[18 + k];
        op[k * 3 + 2] = 1.f / (1.f + expf(-t));
    }
}

// ---------------------------------------------------------------------------
// Kernel 4: fused bilinear sample + bf16 mma.sync GEMM (2-term split, 3 MMAs).
// Tile: 128 px (one (b,h) row) x 128 out, K = 9 taps x 64 ch.
// SMEM tiles (per tap): Ahi/Alo [128px][64ch] bf16, Bhi/Blo [128o][64ch] bf16,
// all with padded row stride 36 words (144B) for conflict-free frag loads.
// 8 warps as 2(m)x4(n); warp tile 64x32; fp32 accum in regs.
// ---------------------------------------------------------------------------
#define RS    36                 // row stride in 32-bit words
#define SM_AHI 0
#define SM_ALO 18432
#define SM_BHI 36864
#define SM_BLO 55296
#define SM_MAIN 73728
#define SD    132                // epilogue staging stride (words)

__global__ void __launch_bounds__(256)
main_kernel(float* __restrict__ out) {
    extern __shared__ __align__(16) char smc[];
    int tid = threadIdx.x, wid = tid >> 5, lid = tid & 31;
    int h = blockIdx.x, b = blockIdx.y;

    int px = tid >> 1, cg = tid & 1;      // sampling: 2 threads/pixel, 32 ch each
    int warp_m = wid & 1, warp_n = wid >> 1;
    int fr = lid >> 2, fc = lid & 3;      // fragment lane decomposition
    int hwb = (b * Hn + h) * Wn;

    float acc[4][4][4];
    #pragma unroll
    for (int i = 0; i < 4; i++)
        #pragma unroll
        for (int j = 0; j < 4; j++)
            #pragma unroll
            for (int q = 0; q < 4; q++) acc[i][j][q] = 0.f;

    for (int k = 0; k < Kn; k++) {
        __syncthreads();   // previous GEMM done reading smem

        // ---- sample A tile for tap k: 32 channels per thread ----
        {
            const float* op = g_off + (hwb + px) * 27 + k * 3;
            float dy = op[0], dx = op[1], m = op[2];
            int ky = k / 3, kx = k - ky * 3;
            float gy = (float)(h - 1 + ky) + dy;
            float gx = (float)(px - 1 + kx) + dx;
            float y0f = floorf(gy), x0f = floorf(gx);
            float wy = gy - y0f, wx = gx - x0f;
            int y0 = (int)y0f, x0i = (int)x0f;

            float4 s[8];
            #pragma unroll
            for (int j = 0; j < 8; j++) s[j] = make_float4(0.f, 0.f, 0.f, 0.f);

            #pragma unroll
            for (int cor = 0; cor < 4; cor++) {
                int yi = y0 + (cor >> 1), xi = x0i + (cor & 1);
                float wgt = ((cor >> 1) ? wy : 1.f - wy) *
                            ((cor & 1)  ? wx : 1.f - wx) * m;
                if (yi < 0 || yi >= Hn || xi < 0 || xi >= Wn) wgt = 0.f;
                int yc = min(max(yi, 0), Hn - 1);
                int xc = min(max(xi, 0), Wn - 1);
                const float4* xp =
                    (const float4*)(g_xt + (((b * Hn + yc) * Wn + xc) << 6) + cg * 32);
                #pragma unroll
                for (int j = 0; j < 8; j++) {
                    float4 v = xp[j];
                    s[j].x += wgt * v.x; s[j].y += wgt * v.y;
                    s[j].z += wgt * v.z; s[j].w += wgt * v.w;
                }
            }
            // split & pack to bf16 pairs: 16 hi words + 16 lo words
            uint32_t hw[16], lw[16];
            #pragma unroll
            for (int j = 0; j < 8; j++) {
                float hx, lx, hy, ly, hz, lz, hwf, lwf;
                split2(s[j].x, hx, lx); split2(s[j].y, hy, ly);
                split2(s[j].z, hz, lz); split2(s[j].w, hwf, lwf);
                hw[2 * j]     = pack_bf16(hx, hy);
                hw[2 * j + 1] = pack_bf16(hz, hwf);
                lw[2 * j]     = pack_bf16(lx, ly);
                lw[2 * j + 1] = pack_bf16(lz, lwf);
            }
            uint32_t wbase = (uint32_t)(px * RS + cg * 16);
            #pragma unroll
            for (int t = 0; t < 4; t++) {
                *(uint4*)(smc + SM_AHI + (wbase + t * 4) * 4) =
                    make_uint4(hw[4*t], hw[4*t+1], hw[4*t+2], hw[4*t+3]);
                *(uint4*)(smc + SM_ALO + (wbase + t * 4) * 4) =
                    make_uint4(lw[4*t], lw[4*t+1], lw[4*t+2], lw[4*t+3]);
            }
        }

        // ---- load B tile for tap k (pre-split bf16) ----
        {
            int o = tid >> 1, kw0 = (tid & 1) * 16;
            const uint4* shi = (const uint4*)(g_wbhi + (k << 12) + o * 32 + kw0);
            const uint4* slo = (const uint4*)(g_wblo + (k << 12) + o * 32 + kw0);
            uint32_t wbase = (uint32_t)(o * RS + kw0);
            #pragma unroll
            for (int t = 0; t < 4; t++) {
                *(uint4*)(smc + SM_BHI + (wbase + t * 4) * 4) = shi[t];
                *(uint4*)(smc + SM_BLO + (wbase + t * 4) * 4) = slo[t];
            }
        }
        __syncthreads();

        // ---- GEMM: 4 k16-steps ----
        #pragma unroll
        for (int s = 0; s < 4; s++) {
            int kb = s * 8 + fc;
            uint32_t bh[4][2], bl[4][2];
            #pragma unroll
            for (int ni = 0; ni < 4; ni++) {
                int nrow = warp_n * 32 + ni * 8 + fr;
                uint32_t w0 = (uint32_t)(nrow * RS + kb);
                bh[ni][0] = *(const uint32_t*)(smc + SM_BHI + w0 * 4);
                bh[ni][1] = *(const uint32_t*)(smc + SM_BHI + (w0 + 4) * 4);
                bl[ni][0] = *(const uint32_t*)(smc + SM_BLO + w0 * 4);
                bl[ni][1] = *(const uint32_t*)(smc + SM_BLO + (w0 + 4) * 4);
            }
            #pragma unroll
            for (int mi = 0; mi < 4; mi++) {
                int row0 = warp_m * 64 + mi * 16 + fr;
                uint32_t w0 = (uint32_t)(row0 * RS + kb);
                uint32_t ah[4], al[4];
                ah[0] = *(const uint32_t*)(smc + SM_AHI + w0 * 4);
                ah[1] = *(const uint32_t*)(smc + SM_AHI + (w0 + 8 * RS) * 4);
                ah[2] = *(const uint32_t*)(smc + SM_AHI + (w0 + 4) * 4);
                ah[3] = *(const uint32_t*)(smc + SM_AHI + (w0 + 8 * RS + 4) * 4);
                al[0] = *(const uint32_t*)(smc + SM_ALO + w0 * 4);
                al[1] = *(const uint32_t*)(smc + SM_ALO + (w0 + 8 * RS) * 4);
                al[2] = *(const uint32_t*)(smc + SM_ALO + (w0 + 4) * 4);
                al[3] = *(const uint32_t*)(smc + SM_ALO + (w0 + 8 * RS + 4) * 4);
                #pragma unroll
                for (int ni = 0; ni < 4; ni++) {
                    mma16816(acc[mi][ni], ah, bh[ni]);
                    mma16816(acc[mi][ni], ah, bl[ni]);
                    mma16816(acc[mi][ni], al, bh[ni]);
                }
            }
        }
    }

    // ---- epilogue: stage D[o][px] in smem, then coalesced STG ----
    __syncthreads();
    float* stg = (float*)smc;
    #pragma unroll
    for (int mi = 0; mi < 4; mi++) {
        int pr = warp_m * 64 + mi * 16 + fr;
        #pragma unroll
        for (int ni = 0; ni < 4; ni++) {
            int oc = warp_n * 32 + ni * 8 + fc * 2;
            stg[oc * SD + pr]           = acc[mi][ni][0];
            stg[(oc + 1) * SD + pr]     = acc[mi][ni][1];
            stg[oc * SD + pr + 8]       = acc[mi][ni][2];
            stg[(oc + 1) * SD + pr + 8] = acc[mi][ni][3];
        }
    }
    __syncthreads();

    #pragma unroll
    for (int t = 0; t < 16; t++) {
        int i4 = tid + t * 256;
        int o = i4 >> 5, p4 = (i4 & 31) * 4;
        float4 v = *(float4*)(stg + o * SD + p4);
        *(float4*)(out + ((size_t)(b * OUTn + o) * Hn + h) * Wn + p4) = v;
    }
}

// ---------------------------------------------------------------------------
extern "C" void kernel_launch(void* const* d_in, const int* in_sizes, int n_in,
                              void* d_out, int out_size) {
    const float* x      = (const float*)d_in[0];
    const float* w_off  = (const float*)d_in[1];
    const float* b_off  = (const float*)d_in[2];
    const float* w_mask = (const float*)d_in[3];
    const float* b_mask = (const float*)d_in[4];
    const float* w_conv = (const float*)d_in[5];
    float* out = (float*)d_out;

    cudaFuncSetAttribute(offmask_kernel,
                         cudaFuncAttributeMaxDynamicSharedMemorySize, 65536);
    cudaFuncSetAttribute(main_kernel,
                         cudaFuncAttributeMaxDynamicSharedMemorySize, SM_MAIN);

    xpose_kernel<<<dim3(4, 128, 8), 256>>>(x);
    wpose_kernel<<<dim3((Kn * OUTn * 32 + 255) / 256), 256>>>(w_conv);

    size_t smA = (size_t)(27 * 576 + 32 + 3 * 130 + 32) * sizeof(float);
    offmask_kernel<<<dim3(Hn, Bn), 128, smA>>>(x, w_off, b_off, w_mask, b_mask);

    main_kernel<<<dim3(Hn, Bn), 256, SM_MAIN>>>(out);
}

// round 4
// speedup vs baseline: 1.2522x; 1.0025x over previous
#include <cuda_runtime.h>
#include <cuda_bf16.h>
#include <math.h>
#include <stdint.h>

#define Bn   8
#define Cn   64
#define Hn   128
#define Wn   128
#define OUTn 128
#define Kn   9

// Scratch (device globals: allocation-free rule)
__device__ float    g_xt  [Bn*Hn*Wn*Cn];   // x transposed to NHWC
__device__ float    g_off [Bn*Hn*Wn*27];   // per-pixel {dy,dx,mask} x 9 taps
__device__ uint32_t g_wbhi[Kn*OUTn*32];    // w_conv bf16-hi, [tap][o][kw] packed pairs
__device__ uint32_t g_wblo[Kn*OUTn*32];    // w_conv bf16-lo

// ---------------------------------------------------------------------------
__device__ __forceinline__ uint32_t smem_u32(const void* p) {
    uint32_t a;
    asm("{ .reg .u64 t; cvta.to.shared.u64 t, %1; cvt.u32.u64 %0, t; }"
        : "=r"(a) : "l"(p));
    return a;
}
__device__ __forceinline__ uint32_t pack_bf16(float a, float b) {
    return (uint32_t)__bfloat16_as_ushort(__float2bfloat16_rn(a)) |
           ((uint32_t)__bfloat16_as_ushort(__float2bfloat16_rn(b)) << 16);
}
__device__ __forceinline__ void split2(float v, float& hi, float& lo) {
    __nv_bfloat16 h = __float2bfloat16_rn(v);
    hi = __bfloat162float(h);
    lo = v - hi;
}
__device__ __forceinline__ void mma16816(float* c, const uint32_t* a, const uint32_t* b) {
    asm volatile(
        "mma.sync.aligned.m16n8k16.row.col.f32.bf16.bf16.f32 "
        "{%0,%1,%2,%3}, {%4,%5,%6,%7}, {%8,%9}, {%0,%1,%2,%3};"
        : "+f"(c[0]), "+f"(c[1]), "+f"(c[2]), "+f"(c[3])
        : "r"(a[0]), "r"(a[1]), "r"(a[2]), "r"(a[3]), "r"(b[0]), "r"(b[1]));
}
__device__ __forceinline__ void ldmx4(uint32_t* r, uint32_t addr) {
    asm volatile(
        "ldmatrix.sync.aligned.m8n8.x4.shared.b16 {%0,%1,%2,%3}, [%4];"
        : "=r"(r[0]), "=r"(r[1]), "=r"(r[2]), "=r"(r[3]) : "r"(addr));
}

// ---------------------------------------------------------------------------
// Kernel 1: transpose x NCHW -> NHWC
// ---------------------------------------------------------------------------
__global__ void xpose_kernel(const float* __restrict__ x) {
    __shared__ float t[64][33];
    int b = blockIdx.z, y = blockIdx.y, x0 = blockIdx.x * 32;
    int tx = threadIdx.x & 31, ty = threadIdx.x >> 5;
    #pragma unroll
    for (int i = 0; i < 8; i++) {
        int c = i * 8 + ty;
        t[c][tx] = x[((b * Cn + c) * Hn + y) * Wn + x0 + tx];
    }
    __syncthreads();
    int c2 = threadIdx.x & 63, col2 = threadIdx.x >> 6;
    #pragma unroll
    for (int j = 0; j < 8; j++) {
        int col = col2 + j * 4;
        g_xt[((b * Hn + y) * Wn + x0 + col) * Cn + c2] = t[c2][col];
    }
}

// ---------------------------------------------------------------------------
// Kernel 2: split w_conv (OUT,C,3,3) into bf16 hi/lo, layout [tap][o][kw]
// ---------------------------------------------------------------------------
__global__ void wpose_kernel(const float* __restrict__ w_conv) {
    int i = blockIdx.x * 256 + threadIdx.x;
    if (i < Kn * OUTn * 32) {
        int tap = i >> 12, rem = i & 4095;
        int o = rem >> 5, kw = rem & 31;
        int c0 = kw * 2;
        float f0 = w_conv[o * 576 + c0 * 9 + tap];
        float f1 = w_conv[o * 576 + (c0 + 1) * 9 + tap];
        float h0, l0, h1, l1;
        split2(f0, h0, l0);
        split2(f1, h1, l1);
        g_wbhi[i] = pack_bf16(h0, h1);
        g_wblo[i] = pack_bf16(l0, l1);
    }
}

// ---------------------------------------------------------------------------
// Kernel 3: fused offset(18ch)+mask(9ch) 3x3 conv, sigmoid on mask.
// Weights repacked [ch][c][12] (48B stride) so each (ch,c) is 2xLDS.128+LDS.32.
// ---------------------------------------------------------------------------
#define WSH_F  (27*64*12)
__global__ void offmask_kernel(const float* __restrict__ x,
                               const float* __restrict__ w_off,
                               const float* __restrict__ b_off,
                               const float* __restrict__ w_mask,
                               const float* __restrict__ b_mask) {
    extern __shared__ float sm[];
    float* wsh = sm;                 // [27][64][12]
    float* bsh = sm + WSH_F;         // 27 (+pad)
    float* xs  = sm + WSH_F + 32;    // 3*130

    int h = blockIdx.x, b = blockIdx.y;
    int tid = threadIdx.x;

    for (int i = tid; i < 27 * 576; i += 128) {
        int ch = i / 576, rem = i - ch * 576;
        int c = rem / 9, j = rem - c * 9;
        float v = (ch < 18) ? w_off[ch * 576 + rem] : w_mask[(ch - 18) * 576 + rem];
        wsh[(ch * 64 + c) * 12 + j] = v;
    }
    if (tid < 27) bsh[tid] = (tid < 18) ? b_off[tid] : b_mask[tid - 18];

    float acc[27];
    #pragma unroll
    for (int i = 0; i < 27; i++) acc[i] = 0.f;

    for (int c = 0; c < Cn; c++) {
        __syncthreads();
        #pragma unroll
        for (int r = 0; r < 3; r++) {
            int y = h + r - 1;
            float v = 0.f;
            if (y >= 0 && y < Hn) v = x[((b * Cn + c) * Hn + y) * Wn + tid];
            xs[r * 130 + tid + 1] = v;
        }
        if (tid < 6) xs[(tid >> 1) * 130 + ((tid & 1) ? 129 : 0)] = 0.f;
        __syncthreads();
        float x00 = xs[tid],       x01 = xs[tid + 1],       x02 = xs[tid + 2];
        float x10 = xs[130 + tid], x11 = xs[130 + tid + 1], x12 = xs[130 + tid + 2];
        float x20 = xs[260 + tid], x21 = xs[260 + tid + 1], x22 = xs[260 + tid + 2];
        #pragma unroll
        for (int ch = 0; ch < 27; ch++) {
            const float* wp = wsh + (ch * 64 + c) * 12;
            float4 wa = *(const float4*)wp;
            float4 wb = *(const float4*)(wp + 4);
            float  w8 = wp[8];
            acc[ch] += wa.x * x00 + wa.y * x01 + wa.z * x02 +
                       wa.w * x10 + wb.x * x11 + wb.y * x12 +
                       wb.z * x20 + wb.w * x21 + w8 * x22;
        }
    }

    float* op = g_off + ((b * Hn + h) * Wn + tid) * 27;
    #pragma unroll
    for (int k = 0; k < Kn; k++) {
        op[k * 3 + 0] = acc[2 * k]     + bsh[2 * k];
        op[k * 3 + 1] = acc[2 * k + 1] + bsh[2 * k + 1];
        float t = acc[18 + k] + bsh[18 + k];
        op[k * 3 + 2] = 1.f / (1.f + expf(-t));
    }
}

// ---------------------------------------------------------------------------
// Kernel 4: fused bilinear sample + bf16 mma.sync GEMM (2-term split, 3 MMAs),
// ldmatrix fragment loads, 2 CTAs/SM.
// ---------------------------------------------------------------------------
#define RS    36                 // row stride in 32-bit words (144B, 16B-aligned)
#define SM_AHI 0
#define SM_ALO 18432
#define SM_BHI 36864
#define SM_BLO 55296
#define SM_MAIN 73728
#define SD    132                // epilogue staging stride (words)

__global__ void __launch_bounds__(256, 2)
main_kernel(float* __restrict__ out) {
    extern __shared__ __align__(16) char smc[];
    uint32_t sb = smem_u32(smc);
    int tid = threadIdx.x, wid = tid >> 5, lid = tid & 31;
    int h = blockIdx.x, b = blockIdx.y;

    int px = tid >> 1, cg = tid & 1;      // sampling: 2 threads/pixel, 32 ch each
    int warp_m = wid & 1, warp_n = wid >> 1;
    int fr = lid >> 2, fc = lid & 3;
    int hwb = (b * Hn + h) * Wn;

    // ldmatrix lane address components (constant per thread)
    uint32_t a_row_l = ((uint32_t)(lid >> 3) & 1) * 8 + (lid & 7);
    uint32_t a_col_l = ((uint32_t)(lid >> 4)) * 16;
    uint32_t b_row_l = ((uint32_t)(lid >> 4)) * 8 + (lid & 7);
    uint32_t b_col_l = ((uint32_t)(lid >> 3) & 1) * 16;

    float acc[4][4][4];
    #pragma unroll
    for (int i = 0; i < 4; i++)
        #pragma unroll
        for (int j = 0; j < 4; j++)
            #pragma unroll
            for (int q = 0; q < 4; q++) acc[i][j][q] = 0.f;

    for (int k = 0; k < Kn; k++) {
        __syncthreads();

        // ---- sample A tile for tap k: 32 channels per thread ----
        {
            const float* op = g_off + (hwb + px) * 27 + k * 3;
            float dy = op[0], dx = op[1], m = op[2];
            int ky = k / 3, kx = k - ky * 3;
            float gy = (float)(h - 1 + ky) + dy;
            float gx = (float)(px - 1 + kx) + dx;
            float y0f = floorf(gy), x0f = floorf(gx);
            float wy = gy - y0f, wx = gx - x0f;
            int y0 = (int)y0f, x0i = (int)x0f;

            float4 s[8];
            #pragma unroll
            for (int j = 0; j < 8; j++) s[j] = make_float4(0.f, 0.f, 0.f, 0.f);

            #pragma unroll
            for (int cor = 0; cor < 4; cor++) {
                int yi = y0 + (cor >> 1), xi = x0i + (cor & 1);
                float wgt = ((cor >> 1) ? wy : 1.f - wy) *
                            ((cor & 1)  ? wx : 1.f - wx) * m;
                if (yi < 0 || yi >= Hn || xi < 0 || xi >= Wn) wgt = 0.f;
                int yc = min(max(yi, 0), Hn - 1);
                int xc = min(max(xi, 0), Wn - 1);
                const float4* xp =
                    (const float4*)(g_xt + (((b * Hn + yc) * Wn + xc) << 6) + cg * 32);
                #pragma unroll
                for (int j = 0; j < 8; j++) {
                    float4 v = xp[j];
                    s[j].x += wgt * v.x; s[j].y += wgt * v.y;
                    s[j].z += wgt * v.z; s[j].w += wgt * v.w;
                }
            }
            uint32_t wbase = (uint32_t)(px * RS + cg * 16);
            #pragma unroll
            for (int t = 0; t < 4; t++) {
                float h0,l0,h1,l1,h2,l2,h3,l3,h4,l4,h5,l5,h6,l6,h7,l7;
                split2(s[2*t].x, h0, l0);   split2(s[2*t].y, h1, l1);
                split2(s[2*t].z, h2, l2);   split2(s[2*t].w, h3, l3);
                split2(s[2*t+1].x, h4, l4); split2(s[2*t+1].y, h5, l5);
                split2(s[2*t+1].z, h6, l6); split2(s[2*t+1].w, h7, l7);
                *(uint4*)(smc + SM_AHI + (wbase + t * 4) * 4) =
                    make_uint4(pack_bf16(h0,h1), pack_bf16(h2,h3),
                               pack_bf16(h4,h5), pack_bf16(h6,h7));
                *(uint4*)(smc + SM_ALO + (wbase + t * 4) * 4) =
                    make_uint4(pack_bf16(l0,l1), pack_bf16(l2,l3),
                               pack_bf16(l4,l5), pack_bf16(l6,l7));
            }
        }

        // ---- load B tile for tap k (pre-split bf16) ----
        {
            int o = tid >> 1, kw0 = (tid & 1) * 16;
            const uint4* shi = (const uint4*)(g_wbhi + (k << 12) + o * 32 + kw0);
            const uint4* slo = (const uint4*)(g_wblo + (k << 12) + o * 32 + kw0);
            uint32_t wbase = (uint32_t)(o * RS + kw0);
            #pragma unroll
            for (int t = 0; t < 4; t++) {
                *(uint4*)(smc + SM_BHI + (wbase + t * 4) * 4) = shi[t];
                *(uint4*)(smc + SM_BLO + (wbase + t * 4) * 4) = slo[t];
            }
        }
        __syncthreads();

        // ---- GEMM: 4 k16-steps, ldmatrix fragment loads ----
        #pragma unroll
        for (int s = 0; s < 4; s++) {
            uint32_t bh[4][2], bl[4][2];
            #pragma unroll
            for (int ni2 = 0; ni2 < 2; ni2++) {
                uint32_t brow = (uint32_t)(warp_n * 32 + ni2 * 16) + b_row_l;
                uint32_t boff = brow * (RS * 4) + (uint32_t)s * 32 + b_col_l;
                uint32_t t0[4], t1[4];
                ldmx4(t0, sb + SM_BHI + boff);
                ldmx4(t1, sb + SM_BLO + boff);
                bh[2*ni2][0] = t0[0]; bh[2*ni2][1] = t0[1];
                bh[2*ni2+1][0] = t0[2]; bh[2*ni2+1][1] = t0[3];
                bl[2*ni2][0] = t1[0]; bl[2*ni2][1] = t1[1];
                bl[2*ni2+1][0] = t1[2]; bl[2*ni2+1][1] = t1[3];
            }
            #pragma unroll
            for (int mi = 0; mi < 4; mi++) {
                uint32_t arow = (uint32_t)(warp_m * 64 + mi * 16) + a_row_l;
                uint32_t aoff = arow * (RS * 4) + (uint32_t)s * 32 + a_col_l;
                uint32_t ah[4], al[4];
                ldmx4(ah, sb + SM_AHI + aoff);
                ldmx4(al, sb + SM_ALO + aoff);
                #pragma unroll
                for (int ni = 0; ni < 4; ni++) {
                    mma16816(acc[mi][ni], ah, bh[ni]);
                    mma16816(acc[mi][ni], ah, bl[ni]);
                    mma16816(acc[mi][ni], al, bh[ni]);
                }
            }
        }
    }

    // ---- epilogue: stage D[o][px] in smem, then coalesced STG ----
    __syncthreads();
    float* stg = (float*)smc;
    #pragma unroll
    for (int mi = 0; mi < 4; mi++) {
        int pr = warp_m * 64 + mi * 16 + fr;
        #pragma unroll
        for (int ni = 0; ni < 4; ni++) {
            int oc = warp_n * 32 + ni * 8 + fc * 2;
            stg[oc * SD + pr]           = acc[mi][ni][0];
            stg[(oc + 1) * SD + pr]     = acc[mi][ni][1];
            stg[oc * SD + pr + 8]       = acc[mi][ni][2];
            stg[(oc + 1) * SD + pr + 8] = acc[mi][ni][3];
        }
    }
    __syncthreads();

    #pragma unroll
    for (int t = 0; t < 16; t++) {
        int i4 = tid + t * 256;
        int o = i4 >> 5, p4 = (i4 & 31) * 4;
        float4 v = *(float4*)(stg + o * SD + p4);
        *(float4*)(out + ((size_t)(b * OUTn + o) * Hn + h) * Wn + p4) = v;
    }
}

// ---------------------------------------------------------------------------
extern "C" void kernel_launch(void* const* d_in, const int* in_sizes, int n_in,
                              void* d_out, int out_size) {
    const float* x      = (const float*)d_in[0];
    const float* w_off  = (const float*)d_in[1];
    const float* b_off  = (const float*)d_in[2];
    const float* w_mask = (const float*)d_in[3];
    const float* b_mask = (const float*)d_in[4];
    const float* w_conv = (const float*)d_in[5];
    float* out = (float*)d_out;

    size_t smA = (size_t)(WSH_F + 32 + 3 * 130 + 32) * sizeof(float);
    cudaFuncSetAttribute(offmask_kernel,
                         cudaFuncAttributeMaxDynamicSharedMemorySize, (int)smA);
    cudaFuncSetAttribute(main_kernel,
                         cudaFuncAttributeMaxDynamicSharedMemorySize, SM_MAIN);

    xpose_kernel<<<dim3(4, 128, 8), 256>>>(x);
    wpose_kernel<<<dim3((Kn * OUTn * 32 + 255) / 256), 256>>>(w_conv);

    offmask_kernel<<<dim3(Hn, Bn), 128, smA>>>(x, w_off, b_off, w_mask, b_mask);

    main_kernel<<<dim3(Hn, Bn), 256, SM_MAIN>>>(out);
}

// round 5
// speedup vs baseline: 2.0877x; 1.6673x over previous
#include <cuda_runtime.h>
#include <cuda_bf16.h>
#include <math.h>
#include <stdint.h>

#define Bn   8
#define Cn   64
#define Hn   128
#define Wn   128
#define OUTn 128
#define Kn   9

// Scratch (device globals: allocation-free rule)
__device__ float    g_xt  [Bn*Hn*Wn*Cn];   // x transposed to NHWC
__device__ float    g_off [Bn*Hn*Wn*27];   // per-pixel {dy,dx,mask} x 9 taps
__device__ uint32_t g_wbhi[Kn*OUTn*32];    // w_conv bf16-hi, [tap][o][kw] packed pairs
__device__ uint32_t g_wblo[Kn*OUTn*32];    // w_conv bf16-lo

// ---------------------------------------------------------------------------
__device__ __forceinline__ uint32_t smem_u32(const void* p) {
    uint32_t a;
    asm("{ .reg .u64 t; cvta.to.shared.u64 t, %1; cvt.u32.u64 %0, t; }"
        : "=r"(a) : "l"(p));
    return a;
}
__device__ __forceinline__ uint32_t pack_bf16(float a, float b) {
    return (uint32_t)__bfloat16_as_ushort(__float2bfloat16_rn(a)) |
           ((uint32_t)__bfloat16_as_ushort(__float2bfloat16_rn(b)) << 16);
}
__device__ __forceinline__ void split2(float v, float& hi, float& lo) {
    __nv_bfloat16 h = __float2bfloat16_rn(v);
    hi = __bfloat162float(h);
    lo = v - hi;
}
__device__ __forceinline__ void mma16816(float* c, const uint32_t* a, const uint32_t* b) {
    asm volatile(
        "mma.sync.aligned.m16n8k16.row.col.f32.bf16.bf16.f32 "
        "{%0,%1,%2,%3}, {%4,%5,%6,%7}, {%8,%9}, {%0,%1,%2,%3};"
        : "+f"(c[0]), "+f"(c[1]), "+f"(c[2]), "+f"(c[3])
        : "r"(a[0]), "r"(a[1]), "r"(a[2]), "r"(a[3]), "r"(b[0]), "r"(b[1]));
}
__device__ __forceinline__ void ldmx4(uint32_t* r, uint32_t addr) {
    asm volatile(
        "ldmatrix.sync.aligned.m8n8.x4.shared.b16 {%0,%1,%2,%3}, [%4];"
        : "=r"(r[0]), "=r"(r[1]), "=r"(r[2]), "=r"(r[3]) : "r"(addr));
}

// ---------------------------------------------------------------------------
// Kernel 1: transpose x NCHW -> NHWC
// ---------------------------------------------------------------------------
__global__ void xpose_kernel(const float* __restrict__ x) {
    __shared__ float t[64][33];
    int b = blockIdx.z, y = blockIdx.y, x0 = blockIdx.x * 32;
    int tx = threadIdx.x & 31, ty = threadIdx.x >> 5;
    #pragma unroll
    for (int i = 0; i < 8; i++) {
        int c = i * 8 + ty;
        t[c][tx] = x[((b * Cn + c) * Hn + y) * Wn + x0 + tx];
    }
    __syncthreads();
    int c2 = threadIdx.x & 63, col2 = threadIdx.x >> 6;
    #pragma unroll
    for (int j = 0; j < 8; j++) {
        int col = col2 + j * 4;
        g_xt[((b * Hn + y) * Wn + x0 + col) * Cn + c2] = t[c2][col];
    }
}

// ---------------------------------------------------------------------------
// Kernel 2: split w_conv (OUT,C,3,3) into bf16 hi/lo, layout [tap][o][kw]
// ---------------------------------------------------------------------------
__global__ void wpose_kernel(const float* __restrict__ w_conv) {
    int i = blockIdx.x * 256 + threadIdx.x;
    if (i < Kn * OUTn * 32) {
        int tap = i >> 12, rem = i & 4095;
        int o = rem >> 5, kw = rem & 31;
        int c0 = kw * 2;
        float f0 = w_conv[o * 576 + c0 * 9 + tap];
        float f1 = w_conv[o * 576 + (c0 + 1) * 9 + tap];
        float h0, l0, h1, l1;
        split2(f0, h0, l0);
        split2(f1, h1, l1);
        g_wbhi[i] = pack_bf16(h0, h1);
        g_wblo[i] = pack_bf16(l0, l1);
    }
}

// ---------------------------------------------------------------------------
// Kernel 3: fused offset(18ch)+mask(9ch) 3x3 conv, sigmoid on mask.
// 512 threads = 4 output rows x 128 px; weights amortized, 32 warps/SM at occ 2.
// ---------------------------------------------------------------------------
#define WSH_F  (27*64*12)
__global__ void __launch_bounds__(512, 2)
offmask_kernel(const float* __restrict__ x,
               const float* __restrict__ w_off,
               const float* __restrict__ b_off,
               const float* __restrict__ w_mask,
               const float* __restrict__ b_mask) {
    extern __shared__ float sm[];
    float* wsh = sm;                 // [27][64][12]
    float* bsh = sm + WSH_F;         // 27 (+pad)
    float* xs  = sm + WSH_F + 32;    // 6*130

    int h4 = blockIdx.x, b = blockIdx.y;
    int tid = threadIdx.x;
    int r = tid >> 7, w = tid & 127;
    int y0 = h4 * 4 - 1;

    for (int i = tid; i < 27 * 576; i += 512) {
        int ch = i / 576, rem = i - ch * 576;
        int c = rem / 9, j = rem - c * 9;
        float v = (ch < 18) ? w_off[ch * 576 + rem] : w_mask[(ch - 18) * 576 + rem];
        wsh[(ch * 64 + c) * 12 + j] = v;
    }
    if (tid < 27) bsh[tid] = (tid < 18) ? b_off[tid] : b_mask[tid - 18];

    float acc[27];
    #pragma unroll
    for (int i = 0; i < 27; i++) acc[i] = 0.f;

    for (int c = 0; c < Cn; c++) {
        __syncthreads();
        for (int i = tid; i < 6 * 128; i += 512) {
            int rr = i >> 7, ww = i & 127;
            int y = y0 + rr;
            float v = (y >= 0 && y < Hn) ? x[((b * Cn + c) * Hn + y) * Wn + ww] : 0.f;
            xs[rr * 130 + ww + 1] = v;
        }
        if (tid < 12) xs[(tid >> 1) * 130 + ((tid & 1) ? 129 : 0)] = 0.f;
        __syncthreads();
        float x00 = xs[r * 130 + w],         x01 = xs[r * 130 + w + 1],         x02 = xs[r * 130 + w + 2];
        float x10 = xs[(r + 1) * 130 + w],   x11 = xs[(r + 1) * 130 + w + 1],   x12 = xs[(r + 1) * 130 + w + 2];
        float x20 = xs[(r + 2) * 130 + w],   x21 = xs[(r + 2) * 130 + w + 1],   x22 = xs[(r + 2) * 130 + w + 2];
        #pragma unroll
        for (int ch = 0; ch < 27; ch++) {
            const float* wp = wsh + (ch * 64 + c) * 12;
            float4 wa = *(const float4*)wp;
            float4 wb = *(const float4*)(wp + 4);
            float  w8 = wp[8];
            acc[ch] += wa.x * x00 + wa.y * x01 + wa.z * x02 +
                       wa.w * x10 + wb.x * x11 + wb.y * x12 +
                       wb.z * x20 + wb.w * x21 + w8 * x22;
        }
    }

    int h = h4 * 4 + r;
    float* op = g_off + ((b * Hn + h) * Wn + w) * 27;
    #pragma unroll
    for (int k = 0; k < Kn; k++) {
        op[k * 3 + 0] = acc[2 * k]     + bsh[2 * k];
        op[k * 3 + 1] = acc[2 * k + 1] + bsh[2 * k + 1];
        float t = acc[18 + k] + bsh[18 + k];
        op[k * 3 + 2] = 1.f / (1.f + expf(-t));
    }
}

// ---------------------------------------------------------------------------
// Kernel 4: fused bilinear sample + bf16 mma.sync GEMM (2-term split, 3 MMAs).
// Coalesced gather: 16 lanes cooperate per (pixel,corner) -> full-128B
// wavefronts (8x fewer L1 wavefronts than round 4). ldmatrix GEMM unchanged.
// ---------------------------------------------------------------------------
#define RS    36                 // row stride in 32-bit words (144B, 16B-aligned)
#define SM_AHI 0
#define SM_ALO 18432
#define SM_BHI 36864
#define SM_BLO 55296
#define SM_MAIN 73728
#define SD    132                // epilogue staging stride (words)

__global__ void __launch_bounds__(256, 2)
main_kernel(float* __restrict__ out) {
    extern __shared__ __align__(16) char smc[];
    uint32_t sb = smem_u32(smc);
    int tid = threadIdx.x, wid = tid >> 5, lid = tid & 31;
    int h = blockIdx.x, b = blockIdx.y;

    int warp_m = wid & 1, warp_n = wid >> 1;
    int fr = lid >> 2, fc = lid & 3;
    int hwb = (b * Hn + h) * Wn;

    // sampling lane mapping: 2 pixels/warp-pass, 16 lanes (=16B chunks) each
    int ppx   = lid >> 4;        // 0/1: which pixel of the pass
    int chunk = lid & 15;        // 4-channel chunk

    // ldmatrix lane address components
    uint32_t a_row_l = ((uint32_t)(lid >> 3) & 1) * 8 + (lid & 7);
    uint32_t a_col_l = ((uint32_t)(lid >> 4)) * 16;
    uint32_t b_row_l = ((uint32_t)(lid >> 4)) * 8 + (lid & 7);
    uint32_t b_col_l = ((uint32_t)(lid >> 3) & 1) * 16;

    float acc[4][4][4];
    #pragma unroll
    for (int i = 0; i < 4; i++)
        #pragma unroll
        for (int j = 0; j < 4; j++)
            #pragma unroll
            for (int q = 0; q < 4; q++) acc[i][j][q] = 0.f;

    for (int k = 0; k < Kn; k++) {
        int ky = k / 3, kx = k - ky * 3;
        __syncthreads();

        // ---- sample A tile for tap k (coalesced, 16 lanes per pixel) ----
        #pragma unroll 4
        for (int pass = 0; pass < 8; pass++) {
            int px = wid * 16 + pass * 2 + ppx;
            const float* op = g_off + (hwb + px) * 27 + k * 3;
            float dy = op[0], dx = op[1], m = op[2];
            float gy = (float)(h - 1 + ky) + dy;
            float gx = (float)(px - 1 + kx) + dx;
            float y0f = floorf(gy), x0f = floorf(gx);
            float wy = gy - y0f, wx = gx - x0f;
            int y0 = (int)y0f, x0i = (int)x0f;

            float s0 = 0.f, s1 = 0.f, s2 = 0.f, s3 = 0.f;
            #pragma unroll
            for (int cor = 0; cor < 4; cor++) {
                int yi = y0 + (cor >> 1), xi = x0i + (cor & 1);
                float wgt = ((cor >> 1) ? wy : 1.f - wy) *
                            ((cor & 1)  ? wx : 1.f - wx) * m;
                if (yi < 0 || yi >= Hn || xi < 0 || xi >= Wn) wgt = 0.f;
                int yc = min(max(yi, 0), Hn - 1);
                int xc = min(max(xi, 0), Wn - 1);
                float4 v = *(const float4*)(
                    g_xt + (((b * Hn + yc) * Wn + xc) << 6) + chunk * 4);
                s0 += wgt * v.x; s1 += wgt * v.y;
                s2 += wgt * v.z; s3 += wgt * v.w;
            }
            float h0, l0, h1, l1, h2, l2, h3, l3;
            split2(s0, h0, l0); split2(s1, h1, l1);
            split2(s2, h2, l2); split2(s3, h3, l3);
            uint32_t wbase = (uint32_t)(px * RS + chunk * 2);
            *(uint2*)(smc + SM_AHI + wbase * 4) =
                make_uint2(pack_bf16(h0, h1), pack_bf16(h2, h3));
            *(uint2*)(smc + SM_ALO + wbase * 4) =
                make_uint2(pack_bf16(l0, l1), pack_bf16(l2, l3));
        }

        // ---- load B tile for tap k (pre-split bf16) ----
        {
            int o = tid >> 1, kw0 = (tid & 1) * 16;
            const uint4* shi = (const uint4*)(g_wbhi + (k << 12) + o * 32 + kw0);
            const uint4* slo = (const uint4*)(g_wblo + (k << 12) + o * 32 + kw0);
            uint32_t wbase = (uint32_t)(o * RS + kw0);
            #pragma unroll
            for (int t = 0; t < 4; t++) {
                *(uint4*)(smc + SM_BHI + (wbase + t * 4) * 4) = shi[t];
                *(uint4*)(smc + SM_BLO + (wbase + t * 4) * 4) = slo[t];
            }
        }
        __syncthreads();

        // ---- GEMM: 4 k16-steps, ldmatrix fragment loads ----
        #pragma unroll
        for (int s = 0; s < 4; s++) {
            uint32_t bh[4][2], bl[4][2];
            #pragma unroll
            for (int ni2 = 0; ni2 < 2; ni2++) {
                uint32_t brow = (uint32_t)(warp_n * 32 + ni2 * 16) + b_row_l;
                uint32_t boff = brow * (RS * 4) + (uint32_t)s * 32 + b_col_l;
                uint32_t t0[4], t1[4];
                ldmx4(t0, sb + SM_BHI + boff);
                ldmx4(t1, sb + SM_BLO + boff);
                bh[2*ni2][0] = t0[0]; bh[2*ni2][1] = t0[1];
                bh[2*ni2+1][0] = t0[2]; bh[2*ni2+1][1] = t0[3];
                bl[2*ni2][0] = t1[0]; bl[2*ni2][1] = t1[1];
                bl[2*ni2+1][0] = t1[2]; bl[2*ni2+1][1] = t1[3];
            }
            #pragma unroll
            for (int mi = 0; mi < 4; mi++) {
                uint32_t arow = (uint32_t)(warp_m * 64 + mi * 16) + a_row_l;
                uint32_t aoff = arow * (RS * 4) + (uint32_t)s * 32 + a_col_l;
                uint32_t ah[4], al[4];
                ldmx4(ah, sb + SM_AHI + aoff);
                ldmx4(al, sb + SM_ALO + aoff);
                #pragma unroll
                for (int ni = 0; ni < 4; ni++) {
                    mma16816(acc[mi][ni], ah, bh[ni]);
                    mma16816(acc[mi][ni], ah, bl[ni]);
                    mma16816(acc[mi][ni], al, bh[ni]);
                }
            }
        }
    }

    // ---- epilogue: stage D[o][px] in smem, then coalesced STG ----
    __syncthreads();
    float* stg = (float*)smc;
    #pragma unroll
    for (int mi = 0; mi < 4; mi++) {
        int pr = warp_m * 64 + mi * 16 + fr;
        #pragma unroll
        for (int ni = 0; ni < 4; ni++) {
            int oc = warp_n * 32 + ni * 8 + fc * 2;
            stg[oc * SD + pr]           = acc[mi][ni][0];
            stg[(oc + 1) * SD + pr]     = acc[mi][ni][1];
            stg[oc * SD + pr + 8]       = acc[mi][ni][2];
            stg[(oc + 1) * SD + pr + 8] = acc[mi][ni][3];
        }
    }
    __syncthreads();

    #pragma unroll
    for (int t = 0; t < 16; t++) {
        int i4 = tid + t * 256;
        int o = i4 >> 5, p4 = (i4 & 31) * 4;
        float4 v = *(float4*)(stg + o * SD + p4);
        *(float4*)(out + ((size_t)(b * OUTn + o) * Hn + h) * Wn + p4) = v;
    }
}

// ---------------------------------------------------------------------------
extern "C" void kernel_launch(void* const* d_in, const int* in_sizes, int n_in,
                              void* d_out, int out_size) {
    const float* x      = (const float*)d_in[0];
    const float* w_off  = (const float*)d_in[1];
    const float* b_off  = (const float*)d_in[2];
    const float* w_mask = (const float*)d_in[3];
    const float* b_mask = (const float*)d_in[4];
    const float* w_conv = (const float*)d_in[5];
    float* out = (float*)d_out;

    size_t smA = (size_t)(WSH_F + 32 + 6 * 130 + 32) * sizeof(float);
    cudaFuncSetAttribute(offmask_kernel,
                         cudaFuncAttributeMaxDynamicSharedMemorySize, (int)smA);
    cudaFuncSetAttribute(main_kernel,
                         cudaFuncAttributeMaxDynamicSharedMemorySize, SM_MAIN);

    xpose_kernel<<<dim3(4, 128, 8), 256>>>(x);
    wpose_kernel<<<dim3((Kn * OUTn * 32 + 255) / 256), 256>>>(w_conv);

    offmask_kernel<<<dim3(Hn / 4, Bn), 512, smA>>>(x, w_off, b_off, w_mask, b_mask);

    main_kernel<<<dim3(Hn, Bn), 256, SM_MAIN>>>(out);
}